// round 16
// baseline (speedup 1.0000x reference)
#include <cuda_runtime.h>
#include <cuda_bf16.h>
#include <cstdint>

#define NLEV 16
#define TBL 524288u
#define PRIME_Y 2654435761u
#define NPTS (1 << 20)
#define NBKT 65536        // 256 x 256 Morton buckets
#define DENSE_TOT 8816565u

// floor(16 * 2^(7l/15)), l = 0..15 — matches numpy fp64 _resolutions()
__constant__ float c_res[NLEV] = {
    16.f, 22.f, 30.f, 42.f, 58.f, 80.f, 111.f, 153.f,
    212.f, 294.f, 406.f, 561.f, 776.f, 1072.f, 1482.f, 2048.f
};
// side = res+1; doff = exclusive prefix of side^2
__constant__ unsigned c_side[NLEV] = {
    17u, 23u, 31u, 43u, 59u, 81u, 112u, 154u,
    213u, 295u, 407u, 562u, 777u, 1073u, 1483u, 2049u
};
__constant__ unsigned c_doff[NLEV] = {
    0u, 289u, 818u, 1779u, 3628u, 7109u, 13670u, 26214u,
    49930u, 95299u, 182324u, 347973u, 663817u, 1267546u, 2418875u, 4618164u
};

// Weight fragments pre-packed in mma.m16n8k16 B-operand order (bf16x2 per reg).
__device__ uint32_t g_B0[2 * 8 * 64];
__device__ uint32_t g_B1[4 * 8 * 64];
__device__ uint32_t g_B2[4 * 1 * 64];

// Sort scratch
__device__ unsigned g_hist[NBKT];
__device__ unsigned g_scan[NBKT];
__device__ unsigned g_bsum[256];
__device__ unsigned g_offs[NBKT];
__device__ __align__(16) float4 g_pts[NPTS];     // {x, y, bits(orig idx), pad}

// Dense de-hashed mirror of all 16 levels (row-major per level), 70.5 MB.
__device__ __align__(16) float2 g_dense[DENSE_TOT];

static __device__ __forceinline__ uint32_t pack_bf16(float lo, float hi) {
    uint32_t r;
    asm("cvt.rn.bf16x2.f32 %0, %1, %2;" : "=r"(r) : "f"(hi), "f"(lo));
    return r;
}

static __device__ __forceinline__ void ldmat4(uint32_t* r, const void* p) {
    uint32_t s = (uint32_t)__cvta_generic_to_shared(p);
    asm volatile("ldmatrix.sync.aligned.m8n8.x4.shared.b16 {%0,%1,%2,%3}, [%4];"
                 : "=r"(r[0]), "=r"(r[1]), "=r"(r[2]), "=r"(r[3]) : "r"(s));
}

static __device__ __forceinline__ void mma16816(float* c, const uint32_t* a, uint2 b) {
    asm volatile("mma.sync.aligned.m16n8k16.row.col.f32.bf16.bf16.f32 "
                 "{%0,%1,%2,%3}, {%4,%5,%6,%7}, {%8,%9}, {%0,%1,%2,%3};"
                 : "+f"(c[0]), "+f"(c[1]), "+f"(c[2]), "+f"(c[3])
                 : "r"(a[0]), "r"(a[1]), "r"(a[2]), "r"(a[3]), "r"(b.x), "r"(b.y));
}

static __device__ __forceinline__ float2 ldg_f2(const float2* p) {
    float2 v;
    asm volatile("ld.global.nc.v2.f32 {%0,%1}, [%2];"
                 : "=f"(v.x), "=f"(v.y) : "l"(p));
    return v;
}

static __device__ __forceinline__ unsigned part1by1(unsigned v) {
    v &= 0xFFu;
    v = (v | (v << 4)) & 0x0F0Fu;
    v = (v | (v << 2)) & 0x3333u;
    v = (v | (v << 1)) & 0x5555u;
    return v;
}
static __device__ __forceinline__ unsigned morton_code(float px, float py) {
    unsigned bx = (unsigned)(px * 256.f);  if (bx > 255u) bx = 255u;
    unsigned by = (unsigned)(py * 256.f);  if (by > 255u) by = 255u;
    return part1by1(bx) | (part1by1(by) << 1);
}

// ---------------- densify: de-hash all levels into row-major grids ----------------
__global__ void densify_kernel(const float* __restrict__ tables) {
    unsigned i = blockIdx.x * 512u + threadIdx.x;
    if (i >= DENSE_TOT) return;
    int l = 0;
    #pragma unroll
    for (int k = 1; k < NLEV; k++) l += (i >= c_doff[k]) ? 1 : 0;
    unsigned q = i - c_doff[l];
    unsigned side = c_side[l];
    unsigned uy = q / side;
    unsigned ux = q - uy * side;
    unsigned idx = (ux ^ (uy * PRIME_Y)) & (TBL - 1u);
    g_dense[i] = __ldg((const float2*)tables + (size_t)l * TBL + idx);
}

// ---------------- fused histogram (2 pts/thread) + weight repack ----------------
__global__ void hist_prep_kernel(const float* __restrict__ x,
                                 const float* __restrict__ W0,
                                 const float* __restrict__ W1,
                                 const float* __restrict__ W2) {
    if (blockIdx.x < 1024) {
        int i = blockIdx.x * 512 + threadIdx.x;
        float4 v = __ldg((const float4*)x + i);
        atomicAdd(&g_hist[morton_code(v.x, v.y)], 1u);
        atomicAdd(&g_hist[morton_code(v.z, v.w)], 1u);
        return;
    }
    int i = (blockIdx.x - 1024) * 512 + threadIdx.x;
    if (i < 1024) {
        int r = i & 1, lane = (i >> 1) & 31, nt = (i >> 6) & 7, kt = i >> 9;
        int tg = lane & 3, g = lane >> 2;
        int k = kt * 16 + tg * 2 + r * 8, n = nt * 8 + g;
        g_B0[i] = pack_bf16(W0[k * 64 + n], W0[(k + 1) * 64 + n]);
    } else if (i < 3072) {
        int j = i - 1024;
        int r = j & 1, lane = (j >> 1) & 31, nt = (j >> 6) & 7, kt = j >> 9;
        int tg = lane & 3, g = lane >> 2;
        int k = kt * 16 + tg * 2 + r * 8, n = nt * 8 + g;
        g_B1[j] = pack_bf16(W1[k * 64 + n], W1[(k + 1) * 64 + n]);
    } else if (i < 3328) {
        int j = i - 3072;
        int r = j & 1, lane = (j >> 1) & 31, kt = j >> 6;
        int tg = lane & 3, g = lane >> 2;
        int k = kt * 16 + tg * 2 + r * 8, n = g;
        float v0 = (n < 3) ? W2[k * 3 + n] : 0.f;
        float v1 = (n < 3) ? W2[(k + 1) * 3 + n] : 0.f;
        g_B2[j] = pack_bf16(v0, v1);
    }
}

__global__ void scanA() {
    __shared__ unsigned s[256];
    const int b = blockIdx.x, t = threadIdx.x, i = b * 256 + t;
    unsigned v = g_hist[i];
    s[t] = v;
    __syncthreads();
    #pragma unroll
    for (int d = 1; d < 256; d <<= 1) {
        unsigned u = (t >= d) ? s[t - d] : 0u;
        __syncthreads();
        if (t >= d) s[t] += u;
        __syncthreads();
    }
    g_scan[i] = s[t];
    if (t == 255) g_bsum[b] = s[255];
}

__global__ void scanBC() {
    __shared__ unsigned s[256];
    const int t = threadIdx.x;
    if (t < 256) s[t] = g_bsum[t];
    __syncthreads();
    #pragma unroll
    for (int d = 1; d < 256; d <<= 1) {
        unsigned u = (t >= d && t < 256) ? s[t - d] : 0u;
        __syncthreads();
        if (t >= d && t < 256) s[t] += u;
        __syncthreads();
    }
    const int i = blockIdx.x * 1024 + t;
    const int b = i >> 8;
    unsigned excl = s[b] - g_bsum[b];
    g_offs[i] = g_scan[i] - g_hist[i] + excl;
    g_hist[i] = 0u;
}

__global__ void scatter_kernel(const float* __restrict__ x) {
    int i = blockIdx.x * blockDim.x + threadIdx.x;
    float4 v = __ldg((const float4*)x + i);
    unsigned i0 = 2u * (unsigned)i, i1 = i0 + 1u;
    unsigned pos0 = atomicAdd(&g_offs[morton_code(v.x, v.y)], 1u);
    unsigned pos1 = atomicAdd(&g_offs[morton_code(v.z, v.w)], 1u);
    g_pts[pos0] = make_float4(v.x, v.y, __uint_as_float(i0), 0.f);
    g_pts[pos1] = make_float4(v.z, v.w, __uint_as_float(i1), 0.f);
}

// ---------------- fused encode + MLP over sorted points, dense tables ----------------
__global__ void __launch_bounds__(128, 4) ngp_fused_mma(
    const float* __restrict__ b0,
    const float* __restrict__ b1,
    const float* __restrict__ b2,
    float* __restrict__ out)
{
    __shared__ __align__(16) unsigned char sA[128 * 144];
    __shared__ __align__(16) unsigned char sB[128 * 144];

    const int tid  = threadIdx.x;
    const int lane = tid & 31;
    const int w    = tid >> 5;
    const int tg   = lane & 3, g = lane >> 2;
    const int rowbase = w * 32;

    const int n = blockIdx.x * 128 + tid;
    const float4 rec = g_pts[n];
    const float2 p = make_float2(rec.x, rec.y);
    const unsigned oid = __float_as_uint(rec.z);

    uint32_t fpack[NLEV];
    #pragma unroll
    for (int half = 0; half < 2; half++) {
        float2 raw[8][4];
        float  txv[8], tyv[8];

        #pragma unroll
        for (int l8 = 0; l8 < 8; l8++) {
            const int l = half * 8 + l8;
            const float res = c_res[l];
            const unsigned side = c_side[l];
            float sx = p.x * res, sy = p.y * res;
            float fx = floorf(sx), fy = floorf(sy);
            txv[l8] = sx - fx;  tyv[l8] = sy - fy;
            unsigned ux = (unsigned)(int)fx;
            unsigned uy = (unsigned)(int)fy;
            const float2* d = g_dense + c_doff[l] + uy * side + ux;
            raw[l8][0] = ldg_f2(d);
            raw[l8][1] = ldg_f2(d + 1);
            raw[l8][2] = ldg_f2(d + side);
            raw[l8][3] = ldg_f2(d + side + 1);
        }

        #pragma unroll
        for (int l8 = 0; l8 < 8; l8++) {
            const float tx = txv[l8], ty = tyv[l8];
            float w00 = (1.f - tx) * (1.f - ty);
            float w10 = tx * (1.f - ty);
            float w01 = (1.f - tx) * ty;
            float w11 = tx * ty;
            float f0 = w00 * raw[l8][0].x + w10 * raw[l8][1].x
                     + w01 * raw[l8][2].x + w11 * raw[l8][3].x;
            float f1 = w00 * raw[l8][0].y + w10 * raw[l8][1].y
                     + w01 * raw[l8][2].y + w11 * raw[l8][3].y;
            fpack[half * 8 + l8] = pack_bf16(f0, f1);
        }
    }
    {
        uint4* dst = (uint4*)(sA + tid * 80);
        dst[0] = make_uint4(fpack[0],  fpack[1],  fpack[2],  fpack[3]);
        dst[1] = make_uint4(fpack[4],  fpack[5],  fpack[6],  fpack[7]);
        dst[2] = make_uint4(fpack[8],  fpack[9],  fpack[10], fpack[11]);
        dst[3] = make_uint4(fpack[12], fpack[13], fpack[14], fpack[15]);
    }
    __syncwarp();

    // ---- layer 0: [32] -> [64], relu ----
    #pragma unroll
    for (int mt = 0; mt < 2; mt++) {
        const int r0 = rowbase + mt * 16;
        uint32_t a[2][4];
        #pragma unroll
        for (int kt = 0; kt < 2; kt++)
            ldmat4(a[kt], sA + (r0 + (lane & 15)) * 80 + kt * 32 + (lane >> 4) * 16);
        float acc[8][4];
        #pragma unroll
        for (int nt = 0; nt < 8; nt++) {
            float2 bz = __ldg((const float2*)b0 + nt * 4 + tg);
            acc[nt][0] = bz.x; acc[nt][1] = bz.y;
            acc[nt][2] = bz.x; acc[nt][3] = bz.y;
        }
        #pragma unroll
        for (int kt = 0; kt < 2; kt++) {
            uint2 Bf[8];
            #pragma unroll
            for (int nt = 0; nt < 8; nt++)
                Bf[nt] = __ldg((const uint2*)g_B0 + (kt * 8 + nt) * 32 + lane);
            #pragma unroll
            for (int nt = 0; nt < 8; nt++)
                mma16816(acc[nt], a[kt], Bf[nt]);
        }
        #pragma unroll
        for (int nt = 0; nt < 8; nt++) {
            const int col = nt * 8 + tg * 2;
            *(uint32_t*)(sB + (r0 + g) * 144 + col * 2) =
                pack_bf16(fmaxf(acc[nt][0], 0.f), fmaxf(acc[nt][1], 0.f));
            *(uint32_t*)(sB + (r0 + g + 8) * 144 + col * 2) =
                pack_bf16(fmaxf(acc[nt][2], 0.f), fmaxf(acc[nt][3], 0.f));
        }
    }
    __syncwarp();

    // ---- layer 1: [64] -> [64], relu ----
    #pragma unroll
    for (int mt = 0; mt < 2; mt++) {
        const int r0 = rowbase + mt * 16;
        uint32_t a[4][4];
        #pragma unroll
        for (int kt = 0; kt < 4; kt++)
            ldmat4(a[kt], sB + (r0 + (lane & 15)) * 144 + kt * 32 + (lane >> 4) * 16);
        float acc[8][4];
        #pragma unroll
        for (int nt = 0; nt < 8; nt++) {
            float2 bz = __ldg((const float2*)b1 + nt * 4 + tg);
            acc[nt][0] = bz.x; acc[nt][1] = bz.y;
            acc[nt][2] = bz.x; acc[nt][3] = bz.y;
        }
        #pragma unroll
        for (int kt = 0; kt < 4; kt++) {
            uint2 Bf[8];
            #pragma unroll
            for (int nt = 0; nt < 8; nt++)
                Bf[nt] = __ldg((const uint2*)g_B1 + (kt * 8 + nt) * 32 + lane);
            #pragma unroll
            for (int nt = 0; nt < 8; nt++)
                mma16816(acc[nt], a[kt], Bf[nt]);
        }
        #pragma unroll
        for (int nt = 0; nt < 8; nt++) {
            const int col = nt * 8 + tg * 2;
            *(uint32_t*)(sA + (r0 + g) * 144 + col * 2) =
                pack_bf16(fmaxf(acc[nt][0], 0.f), fmaxf(acc[nt][1], 0.f));
            *(uint32_t*)(sA + (r0 + g + 8) * 144 + col * 2) =
                pack_bf16(fmaxf(acc[nt][2], 0.f), fmaxf(acc[nt][3], 0.f));
        }
    }
    __syncwarp();

    // ---- layer 2: [64] -> [3], sigmoid ----
    {
        uint2 Bf2[4];
        #pragma unroll
        for (int kt = 0; kt < 4; kt++)
            Bf2[kt] = __ldg((const uint2*)g_B2 + kt * 32 + lane);
        float bx = (tg == 0) ? __ldg(b2 + 0) : (tg == 1 ? __ldg(b2 + 2) : 0.f);
        float by = (tg == 0) ? __ldg(b2 + 1) : 0.f;

        unsigned char* osm = sB + w * (32 * 144);

        #pragma unroll
        for (int mt = 0; mt < 2; mt++) {
            const int r0 = rowbase + mt * 16;
            uint32_t a[4][4];
            #pragma unroll
            for (int kt = 0; kt < 4; kt++)
                ldmat4(a[kt], sA + (r0 + (lane & 15)) * 144 + kt * 32 + (lane >> 4) * 16);
            float acc[4] = {bx, by, bx, by};
            #pragma unroll
            for (int kt = 0; kt < 4; kt++)
                mma16816(acc, a[kt], Bf2[kt]);

            float s0 = 1.f / (1.f + __expf(-acc[0]));
            float s1 = 1.f / (1.f + __expf(-acc[1]));
            float s2 = 1.f / (1.f + __expf(-acc[2]));
            float s3 = 1.f / (1.f + __expf(-acc[3]));
            if (tg < 2) {
                const int lr = mt * 16 + g;
                *(float2*)(osm + lr * 16 + tg * 8)       = make_float2(s0, s1);
                *(float2*)(osm + (lr + 8) * 16 + tg * 8) = make_float2(s2, s3);
            }
        }
    }
    __syncwarp();

    // ---- store: each thread writes its point's 3 outputs ----
    {
        const float4 v = *(const float4*)(sB + w * (32 * 144) + lane * 16);
        float* o = out + 3u * oid;
        o[0] = v.x; o[1] = v.y; o[2] = v.z;
    }
}

extern "C" void kernel_launch(void* const* d_in, const int* in_sizes, int n_in,
                              void* d_out, int out_size) {
    const float* x      = (const float*)d_in[0];
    const float* tables = (const float*)d_in[1];
    const float* W0     = (const float*)d_in[2];
    const float* b0     = (const float*)d_in[3];
    const float* W1     = (const float*)d_in[4];
    const float* b1     = (const float*)d_in[5];
    const float* W2     = (const float*)d_in[6];
    const float* b2     = (const float*)d_in[7];
    float* out = (float*)d_out;

    const int n = in_sizes[0] / 2;            // N points (1048576)

    densify_kernel<<<(DENSE_TOT + 511u) / 512u, 512>>>(tables);
    hist_prep_kernel<<<1024 + 7, 512>>>(x, W0, W1, W2);
    scanA<<<256, 256>>>();
    scanBC<<<NBKT / 1024, 1024>>>();
    scatter_kernel<<<n / 1024, 512>>>(x);
    ngp_fused_mma<<<n / 128, 128>>>(b0, b1, b2, out);
}

// round 17
// speedup vs baseline: 1.3903x; 1.3903x over previous
#include <cuda_runtime.h>
#include <cuda_bf16.h>
#include <cstdint>

#define NLEV 16
#define TBL 524288u
#define PRIME_Y 2654435761u
#define NPTS (1 << 20)
#define NBKT 65536   // 256 x 256 Morton buckets

// floor(16 * 2^(7l/15)), l = 0..15 — matches numpy fp64 _resolutions()
__constant__ float c_res[NLEV] = {
    16.f, 22.f, 30.f, 42.f, 58.f, 80.f, 111.f, 153.f,
    212.f, 294.f, 406.f, 561.f, 776.f, 1072.f, 1482.f, 2048.f
};

// Weight fragments pre-packed in mma.m16n8k16 B-operand order (bf16x2 per reg).
__device__ uint32_t g_B0[2 * 8 * 64];
__device__ uint32_t g_B1[4 * 8 * 64];
__device__ uint32_t g_B2[4 * 1 * 64];

// Sort scratch (static device globals; zero-initialized at module load)
__device__ unsigned g_hist[NBKT];
__device__ unsigned g_scan[NBKT];
__device__ unsigned g_bsum[256];
__device__ unsigned g_offs[NBKT];
__device__ __align__(16) float4 g_pts[NPTS];   // {x, y, bits(orig idx), pad}

static __device__ __forceinline__ uint32_t pack_bf16(float lo, float hi) {
    uint32_t r;
    asm("cvt.rn.bf16x2.f32 %0, %1, %2;" : "=r"(r) : "f"(hi), "f"(lo));
    return r;
}

static __device__ __forceinline__ void ldmat4(uint32_t* r, const void* p) {
    uint32_t s = (uint32_t)__cvta_generic_to_shared(p);
    asm volatile("ldmatrix.sync.aligned.m8n8.x4.shared.b16 {%0,%1,%2,%3}, [%4];"
                 : "=r"(r[0]), "=r"(r[1]), "=r"(r[2]), "=r"(r[3]) : "r"(s));
}

static __device__ __forceinline__ void mma16816(float* c, const uint32_t* a, uint2 b) {
    asm volatile("mma.sync.aligned.m16n8k16.row.col.f32.bf16.bf16.f32 "
                 "{%0,%1,%2,%3}, {%4,%5,%6,%7}, {%8,%9}, {%0,%1,%2,%3};"
                 : "+f"(c[0]), "+f"(c[1]), "+f"(c[2]), "+f"(c[3])
                 : "r"(a[0]), "r"(a[1]), "r"(a[2]), "r"(a[3]), "r"(b.x), "r"(b.y));
}

static __device__ __forceinline__ float2 ldg_f2(const float2* p) {
    float2 v;
    asm volatile("ld.global.nc.v2.f32 {%0,%1}, [%2];"
                 : "=f"(v.x), "=f"(v.y) : "l"(p));
    return v;
}

static __device__ __forceinline__ unsigned part1by1(unsigned v) {
    v &= 0xFFu;
    v = (v | (v << 4)) & 0x0F0Fu;
    v = (v | (v << 2)) & 0x3333u;
    v = (v | (v << 1)) & 0x5555u;
    return v;
}
static __device__ __forceinline__ unsigned morton_code(float px, float py) {
    unsigned bx = (unsigned)(px * 256.f);  if (bx > 255u) bx = 255u;
    unsigned by = (unsigned)(py * 256.f);  if (by > 255u) by = 255u;
    return part1by1(bx) | (part1by1(by) << 1);
}

// ---------------- fused histogram (2 pts/thread) + weight repack ----------------
__global__ void hist_prep_kernel(const float* __restrict__ x,
                                 const float* __restrict__ W0,
                                 const float* __restrict__ W1,
                                 const float* __restrict__ W2) {
    if (blockIdx.x < 1024) {
        int i = blockIdx.x * 512 + threadIdx.x;
        float4 v = __ldg((const float4*)x + i);
        atomicAdd(&g_hist[morton_code(v.x, v.y)], 1u);
        atomicAdd(&g_hist[morton_code(v.z, v.w)], 1u);
        return;
    }
    int i = (blockIdx.x - 1024) * 512 + threadIdx.x;
    if (i < 1024) {
        int r = i & 1, lane = (i >> 1) & 31, nt = (i >> 6) & 7, kt = i >> 9;
        int tg = lane & 3, g = lane >> 2;
        int k = kt * 16 + tg * 2 + r * 8, n = nt * 8 + g;
        g_B0[i] = pack_bf16(W0[k * 64 + n], W0[(k + 1) * 64 + n]);
    } else if (i < 3072) {
        int j = i - 1024;
        int r = j & 1, lane = (j >> 1) & 31, nt = (j >> 6) & 7, kt = j >> 9;
        int tg = lane & 3, g = lane >> 2;
        int k = kt * 16 + tg * 2 + r * 8, n = nt * 8 + g;
        g_B1[j] = pack_bf16(W1[k * 64 + n], W1[(k + 1) * 64 + n]);
    } else if (i < 3328) {
        int j = i - 3072;
        int r = j & 1, lane = (j >> 1) & 31, kt = j >> 6;
        int tg = lane & 3, g = lane >> 2;
        int k = kt * 16 + tg * 2 + r * 8, n = g;
        float v0 = (n < 3) ? W2[k * 3 + n] : 0.f;
        float v1 = (n < 3) ? W2[(k + 1) * 3 + n] : 0.f;
        g_B2[j] = pack_bf16(v0, v1);
    }
}

__global__ void scanA() {
    __shared__ unsigned s[256];
    const int b = blockIdx.x, t = threadIdx.x, i = b * 256 + t;
    unsigned v = g_hist[i];
    s[t] = v;
    __syncthreads();
    #pragma unroll
    for (int d = 1; d < 256; d <<= 1) {
        unsigned u = (t >= d) ? s[t - d] : 0u;
        __syncthreads();
        if (t >= d) s[t] += u;
        __syncthreads();
    }
    g_scan[i] = s[t];
    if (t == 255) g_bsum[b] = s[255];
}

__global__ void scanBC() {
    __shared__ unsigned s[256];
    const int t = threadIdx.x;
    if (t < 256) s[t] = g_bsum[t];
    __syncthreads();
    #pragma unroll
    for (int d = 1; d < 256; d <<= 1) {
        unsigned u = (t >= d && t < 256) ? s[t - d] : 0u;
        __syncthreads();
        if (t >= d && t < 256) s[t] += u;
        __syncthreads();
    }
    const int i = blockIdx.x * 1024 + t;
    const int b = i >> 8;
    unsigned excl = s[b] - g_bsum[b];
    g_offs[i] = g_scan[i] - g_hist[i] + excl;
    g_hist[i] = 0u;
}

__global__ void scatter_kernel(const float* __restrict__ x) {
    int i = blockIdx.x * blockDim.x + threadIdx.x;
    float4 v = __ldg((const float4*)x + i);
    unsigned i0 = 2u * (unsigned)i, i1 = i0 + 1u;
    unsigned pos0 = atomicAdd(&g_offs[morton_code(v.x, v.y)], 1u);
    unsigned pos1 = atomicAdd(&g_offs[morton_code(v.z, v.w)], 1u);
    g_pts[pos0] = make_float4(v.x, v.y, __uint_as_float(i0), 0.f);
    g_pts[pos1] = make_float4(v.z, v.w, __uint_as_float(i1), 0.f);
}

// ---------------- fused encode + MLP over sorted points ----------------
__global__ void __launch_bounds__(128, 4) ngp_fused_mma(
    const float* __restrict__ tables,
    const float* __restrict__ b0,
    const float* __restrict__ b1,
    const float* __restrict__ b2,
    float* __restrict__ out)
{
    __shared__ __align__(16) unsigned char sA[128 * 144];
    __shared__ __align__(16) unsigned char sB[128 * 144];

    const int tid  = threadIdx.x;
    const int lane = tid & 31;
    const int w    = tid >> 5;
    const int tg   = lane & 3, g = lane >> 2;
    const int rowbase = w * 32;

    const int n = blockIdx.x * 128 + tid;
    const float4 rec = g_pts[n];
    const float2 p = make_float2(rec.x, rec.y);
    const unsigned oid = __float_as_uint(rec.z);

    // ---- hash-grid encode (batched loads per 8-level half) ----
    uint32_t fpack[NLEV];
    #pragma unroll
    for (int half = 0; half < 2; half++) {
        float2 raw[8][4];
        float  txv[8], tyv[8];

        #pragma unroll
        for (int l8 = 0; l8 < 8; l8++) {
            const int l = half * 8 + l8;
            const float res = c_res[l];
            float sx = p.x * res, sy = p.y * res;
            float fx = floorf(sx), fy = floorf(sy);
            txv[l8] = sx - fx;  tyv[l8] = sy - fy;
            unsigned ux = (unsigned)(int)fx;
            unsigned uy = (unsigned)(int)fy;
            unsigned hy0 = uy * PRIME_Y;
            unsigned hy1 = (uy + 1u) * PRIME_Y;
            const float2* tb = (const float2*)tables + (size_t)l * TBL;
            raw[l8][0] = ldg_f2(tb + (( ux       ^ hy0) & (TBL - 1u)));
            raw[l8][1] = ldg_f2(tb + (((ux + 1u) ^ hy0) & (TBL - 1u)));
            raw[l8][2] = ldg_f2(tb + (( ux       ^ hy1) & (TBL - 1u)));
            raw[l8][3] = ldg_f2(tb + (((ux + 1u) ^ hy1) & (TBL - 1u)));
        }

        #pragma unroll
        for (int l8 = 0; l8 < 8; l8++) {
            const float tx = txv[l8], ty = tyv[l8];
            float w00 = (1.f - tx) * (1.f - ty);
            float w10 = tx * (1.f - ty);
            float w01 = (1.f - tx) * ty;
            float w11 = tx * ty;
            float f0 = w00 * raw[l8][0].x + w10 * raw[l8][1].x
                     + w01 * raw[l8][2].x + w11 * raw[l8][3].x;
            float f1 = w00 * raw[l8][0].y + w10 * raw[l8][1].y
                     + w01 * raw[l8][2].y + w11 * raw[l8][3].y;
            fpack[half * 8 + l8] = pack_bf16(f0, f1);
        }
    }
    {
        uint4* dst = (uint4*)(sA + tid * 80);
        dst[0] = make_uint4(fpack[0],  fpack[1],  fpack[2],  fpack[3]);
        dst[1] = make_uint4(fpack[4],  fpack[5],  fpack[6],  fpack[7]);
        dst[2] = make_uint4(fpack[8],  fpack[9],  fpack[10], fpack[11]);
        dst[3] = make_uint4(fpack[12], fpack[13], fpack[14], fpack[15]);
    }
    __syncwarp();

    // ---- layer 0: [32] -> [64], relu. kt-outer, both 16-row m-tiles share Bf loads ----
    {
        float acc0[8][4], acc1[8][4];
        #pragma unroll
        for (int nt = 0; nt < 8; nt++) {
            float2 bz = __ldg((const float2*)b0 + nt * 4 + tg);
            acc0[nt][0] = bz.x; acc0[nt][1] = bz.y; acc0[nt][2] = bz.x; acc0[nt][3] = bz.y;
            acc1[nt][0] = bz.x; acc1[nt][1] = bz.y; acc1[nt][2] = bz.x; acc1[nt][3] = bz.y;
        }
        #pragma unroll
        for (int kt = 0; kt < 2; kt++) {
            uint32_t a0[4], a1[4];
            ldmat4(a0, sA + (rowbase +      (lane & 15)) * 80 + kt * 32 + (lane >> 4) * 16);
            ldmat4(a1, sA + (rowbase + 16 + (lane & 15)) * 80 + kt * 32 + (lane >> 4) * 16);
            uint2 Bf[8];
            #pragma unroll
            for (int nt = 0; nt < 8; nt++)
                Bf[nt] = __ldg((const uint2*)g_B0 + (kt * 8 + nt) * 32 + lane);
            #pragma unroll
            for (int nt = 0; nt < 8; nt++) {
                mma16816(acc0[nt], a0, Bf[nt]);
                mma16816(acc1[nt], a1, Bf[nt]);
            }
        }
        #pragma unroll
        for (int nt = 0; nt < 8; nt++) {
            const int col = nt * 8 + tg * 2;
            *(uint32_t*)(sB + (rowbase + g) * 144 + col * 2) =
                pack_bf16(fmaxf(acc0[nt][0], 0.f), fmaxf(acc0[nt][1], 0.f));
            *(uint32_t*)(sB + (rowbase + g + 8) * 144 + col * 2) =
                pack_bf16(fmaxf(acc0[nt][2], 0.f), fmaxf(acc0[nt][3], 0.f));
            *(uint32_t*)(sB + (rowbase + 16 + g) * 144 + col * 2) =
                pack_bf16(fmaxf(acc1[nt][0], 0.f), fmaxf(acc1[nt][1], 0.f));
            *(uint32_t*)(sB + (rowbase + 16 + g + 8) * 144 + col * 2) =
                pack_bf16(fmaxf(acc1[nt][2], 0.f), fmaxf(acc1[nt][3], 0.f));
        }
    }
    __syncwarp();

    // ---- layer 1: [64] -> [64], relu. kt-outer, both m-tiles share Bf loads ----
    {
        float acc0[8][4], acc1[8][4];
        #pragma unroll
        for (int nt = 0; nt < 8; nt++) {
            float2 bz = __ldg((const float2*)b1 + nt * 4 + tg);
            acc0[nt][0] = bz.x; acc0[nt][1] = bz.y; acc0[nt][2] = bz.x; acc0[nt][3] = bz.y;
            acc1[nt][0] = bz.x; acc1[nt][1] = bz.y; acc1[nt][2] = bz.x; acc1[nt][3] = bz.y;
        }
        #pragma unroll
        for (int kt = 0; kt < 4; kt++) {
            uint32_t a0[4], a1[4];
            ldmat4(a0, sB + (rowbase +      (lane & 15)) * 144 + kt * 32 + (lane >> 4) * 16);
            ldmat4(a1, sB + (rowbase + 16 + (lane & 15)) * 144 + kt * 32 + (lane >> 4) * 16);
            uint2 Bf[8];
            #pragma unroll
            for (int nt = 0; nt < 8; nt++)
                Bf[nt] = __ldg((const uint2*)g_B1 + (kt * 8 + nt) * 32 + lane);
            #pragma unroll
            for (int nt = 0; nt < 8; nt++) {
                mma16816(acc0[nt], a0, Bf[nt]);
                mma16816(acc1[nt], a1, Bf[nt]);
            }
        }
        #pragma unroll
        for (int nt = 0; nt < 8; nt++) {
            const int col = nt * 8 + tg * 2;
            *(uint32_t*)(sA + (rowbase + g) * 144 + col * 2) =
                pack_bf16(fmaxf(acc0[nt][0], 0.f), fmaxf(acc0[nt][1], 0.f));
            *(uint32_t*)(sA + (rowbase + g + 8) * 144 + col * 2) =
                pack_bf16(fmaxf(acc0[nt][2], 0.f), fmaxf(acc0[nt][3], 0.f));
            *(uint32_t*)(sA + (rowbase + 16 + g) * 144 + col * 2) =
                pack_bf16(fmaxf(acc1[nt][0], 0.f), fmaxf(acc1[nt][1], 0.f));
            *(uint32_t*)(sA + (rowbase + 16 + g + 8) * 144 + col * 2) =
                pack_bf16(fmaxf(acc1[nt][2], 0.f), fmaxf(acc1[nt][3], 0.f));
        }
    }
    __syncwarp();

    // ---- layer 2: [64] -> [3], sigmoid ----
    {
        uint2 Bf2[4];
        #pragma unroll
        for (int kt = 0; kt < 4; kt++)
            Bf2[kt] = __ldg((const uint2*)g_B2 + kt * 32 + lane);
        float bx = (tg == 0) ? __ldg(b2 + 0) : (tg == 1 ? __ldg(b2 + 2) : 0.f);
        float by = (tg == 0) ? __ldg(b2 + 1) : 0.f;

        unsigned char* osm = sB + w * (32 * 144);

        #pragma unroll
        for (int mt = 0; mt < 2; mt++) {
            const int r0 = rowbase + mt * 16;
            uint32_t a[4][4];
            #pragma unroll
            for (int kt = 0; kt < 4; kt++)
                ldmat4(a[kt], sA + (r0 + (lane & 15)) * 144 + kt * 32 + (lane >> 4) * 16);
            float acc[4] = {bx, by, bx, by};
            #pragma unroll
            for (int kt = 0; kt < 4; kt++)
                mma16816(acc, a[kt], Bf2[kt]);

            float s0 = 1.f / (1.f + __expf(-acc[0]));
            float s1 = 1.f / (1.f + __expf(-acc[1]));
            float s2 = 1.f / (1.f + __expf(-acc[2]));
            float s3 = 1.f / (1.f + __expf(-acc[3]));
            if (tg < 2) {
                const int lr = mt * 16 + g;
                *(float2*)(osm + lr * 16 + tg * 8)       = make_float2(s0, s1);
                *(float2*)(osm + (lr + 8) * 16 + tg * 8) = make_float2(s2, s3);
            }
        }
    }
    __syncwarp();

    // ---- store: each thread writes its point's 3 outputs (scalar STG.32, known-good) ----
    {
        const float4 v = *(const float4*)(sB + w * (32 * 144) + lane * 16);
        float* o = out + 3u * oid;
        o[0] = v.x; o[1] = v.y; o[2] = v.z;
    }
}

extern "C" void kernel_launch(void* const* d_in, const int* in_sizes, int n_in,
                              void* d_out, int out_size) {
    const float* x      = (const float*)d_in[0];
    const float* tables = (const float*)d_in[1];
    const float* W0     = (const float*)d_in[2];
    const float* b0     = (const float*)d_in[3];
    const float* W1     = (const float*)d_in[4];
    const float* b1     = (const float*)d_in[5];
    const float* W2     = (const float*)d_in[6];
    const float* b2     = (const float*)d_in[7];
    float* out = (float*)d_out;

    const int n = in_sizes[0] / 2;            // N points (1048576)

    hist_prep_kernel<<<1024 + 7, 512>>>(x, W0, W1, W2);
    scanA<<<256, 256>>>();
    scanBC<<<NBKT / 1024, 1024>>>();
    scatter_kernel<<<n / 1024, 512>>>(x);
    ngp_fused_mma<<<n / 128, 128>>>(tables, b0, b1, b2, out);
}